// round 1
// baseline (speedup 1.0000x reference)
#include <cuda_runtime.h>
#include <math.h>

#define BB 8
#define CC 512
#define CQ 64
#define NN 4096   // H*W = 64*64

// ---------------- scratch (static device arrays: allowed) ----------------
__device__ float d_f[(size_t)BB * NN * CQ];          // keys   f : (b, i, d)  8 MB
__device__ float d_g[(size_t)BB * NN * CQ];          // queries g: (b, j, d)  8 MB
__device__ float d_h[(size_t)BB * NN * CC];          // values h : (b, i, c) 64 MB
__device__ float d_rsig[3];                          // 1/sigma for Wf, Wg, Wh

// ---------------- 1) spectral sigma: sigma = ||W v||, v = normalize(W^T u) -----
__global__ void sigma_kernel(const float* __restrict__ Wf, const float* __restrict__ Wg,
                             const float* __restrict__ Wh, const float* __restrict__ uf,
                             const float* __restrict__ ug, const float* __restrict__ uh) {
    const int w = blockIdx.x;
    const float* W; const float* u; int M;
    if (w == 0)      { W = Wf; u = uf; M = CQ; }
    else if (w == 1) { W = Wg; u = ug; M = CQ; }
    else             { W = Wh; u = uh; M = CC; }
    const int K = CC;

    __shared__ float t[CC];
    __shared__ float red[CC];
    __shared__ float vnorm;
    const int tid = threadIdx.x;  // 512 threads

    // t = W^T u  (each thread owns column tid)
    float acc = 0.f;
    for (int m = 0; m < M; m++) acc += W[m * K + tid] * u[m];
    t[tid] = acc;
    red[tid] = acc * acc;
    __syncthreads();
    for (int s = 256; s > 0; s >>= 1) { if (tid < s) red[tid] += red[tid + s]; __syncthreads(); }
    if (tid == 0) vnorm = sqrtf(red[0]) + 1e-12f;
    __syncthreads();
    t[tid] *= (1.f / vnorm);   // t := v
    __syncthreads();

    // w = W v ; sigma = ||w||^2 / (||w|| + 1e-12)
    float wsq = 0.f;
    for (int m = tid; m < M; m += 512) {
        float a = 0.f;
        for (int k = 0; k < K; k++) a += W[m * K + k] * t[k];
        wsq += a * a;
    }
    red[tid] = wsq;
    __syncthreads();
    for (int s = 256; s > 0; s >>= 1) { if (tid < s) red[tid] += red[tid + s]; __syncthreads(); }
    if (tid == 0) {
        float nw2 = red[0];
        float nw  = sqrtf(nw2);
        float sigma = nw2 / (nw + 1e-12f);
        d_rsig[w] = 1.f / sigma;
    }
}

// ---------------- 2) fused projection GEMM: (f,g,h) = W_seg/sigma @ x + b -------
// Combined output rows: [0,64)=f, [64,128)=g, [128,640)=h. Tile 64x64, K-chunk 32.
__global__ void __launch_bounds__(256) proj_kernel(
    const float* __restrict__ x,
    const float* __restrict__ Wf, const float* __restrict__ bf,
    const float* __restrict__ Wg, const float* __restrict__ bg,
    const float* __restrict__ Wh, const float* __restrict__ bh) {
    const int K = CC;
    const int n0 = blockIdx.x * 64;
    const int o0 = blockIdx.y * 64;     // combined o in [0,640)
    const int b  = blockIdx.z;

    const float* W; const float* bias; int seg, orow0;
    if (o0 < 64)       { seg = 0; W = Wf; bias = bf; orow0 = o0; }
    else if (o0 < 128) { seg = 1; W = Wg; bias = bg; orow0 = o0 - 64; }
    else               { seg = 2; W = Wh; bias = bh; orow0 = o0 - 128; }
    const float rs = d_rsig[seg];

    __shared__ float Ws[32][69];   // [kk][oo], pad 69: conflict-free transposed store
    __shared__ float xs[32][68];   // [kk][nn], pad 68: 16B-aligned rows for float4

    const int tid = threadIdx.y * 16 + threadIdx.x;
    const int tx = threadIdx.x, ty = threadIdx.y;

    float accr[4][4];
#pragma unroll
    for (int i = 0; i < 4; i++)
#pragma unroll
        for (int j = 0; j < 4; j++) accr[i][j] = 0.f;

    const size_t xbase = (size_t)b * CC * NN;

    for (int kc = 0; kc < K; kc += 32) {
        // load x tile: xs[kk][nn] = x[b, kc+kk, n0+nn]
#pragma unroll
        for (int r = 0; r < 8; r++) {
            int e = tid + 256 * r;           // e in [0,2048)
            int kk = e >> 6, nn = e & 63;
            xs[kk][nn] = x[xbase + (size_t)(kc + kk) * NN + n0 + nn];
        }
        // load W tile transposed: Ws[kk][oo] = W[orow0+oo][kc+kk]
#pragma unroll
        for (int r = 0; r < 8; r++) {
            int e = tid + 256 * r;
            int kk = e & 31, oo = e >> 5;
            Ws[kk][oo] = W[(size_t)(orow0 + oo) * K + kc + kk];
        }
        __syncthreads();
#pragma unroll
        for (int kk = 0; kk < 32; kk++) {
            float a0 = Ws[kk][ty * 4 + 0];
            float a1 = Ws[kk][ty * 4 + 1];
            float a2 = Ws[kk][ty * 4 + 2];
            float a3 = Ws[kk][ty * 4 + 3];
            float4 bv = *(const float4*)&xs[kk][tx * 4];
            accr[0][0] += a0 * bv.x; accr[0][1] += a0 * bv.y; accr[0][2] += a0 * bv.z; accr[0][3] += a0 * bv.w;
            accr[1][0] += a1 * bv.x; accr[1][1] += a1 * bv.y; accr[1][2] += a1 * bv.z; accr[1][3] += a1 * bv.w;
            accr[2][0] += a2 * bv.x; accr[2][1] += a2 * bv.y; accr[2][2] += a2 * bv.z; accr[2][3] += a2 * bv.w;
            accr[3][0] += a3 * bv.x; accr[3][1] += a3 * bv.y; accr[3][2] += a3 * bv.z; accr[3][3] += a3 * bv.w;
        }
        __syncthreads();
    }

    // epilogue: scale by 1/sigma, add bias, write to (b, n, o) layouts
#pragma unroll
    for (int i = 0; i < 4; i++) {
        const int orow = orow0 + ty * 4 + i;       // local row within segment
        const float bia = bias[orow];
#pragma unroll
        for (int j = 0; j < 4; j++) {
            const int n = n0 + tx * 4 + j;
            const float v = accr[i][j] * rs + bia;
            if (seg == 0)      d_f[((size_t)b * NN + n) * CQ + orow] = v;
            else if (seg == 1) d_g[((size_t)b * NN + n) * CQ + orow] = v;
            else               d_h[((size_t)b * NN + n) * CC + orow] = v;
        }
    }
}

// ---------------- 3) flash attention -------------------------------------------
// Per block: 32 queries (j), stream keys in tiles of 32 (i).
// beta[:,j] = softmax_i(f_i . g_j); o[:,j] = sum_i beta * h_i; y = gamma*o + x.
__global__ void __launch_bounds__(256, 2) attn_kernel(
    const float* __restrict__ x, const float* __restrict__ gamma,
    float* __restrict__ out) {
    const int b  = blockIdx.y;
    const int j0 = blockIdx.x * 32;
    const int tid = threadIdx.x;
    const int lane = tid & 31, warp = tid >> 5;

    __shared__ float gs[32][68];         // g[j][d]
    __shared__ float fs[32][68];         // f[i][d]
    __shared__ float Ps[32][33];         // exp(S - mnew)
    __shared__ float m_s[32], l_s[32], scale_s[32];

    // load queries
    const float* gbase = d_g + ((size_t)b * NN + j0) * CQ;
    for (int e = tid; e < 32 * 64; e += 256) gs[e >> 6][e & 63] = gbase[e];
    if (tid < 32) { m_s[tid] = -INFINITY; l_s[tid] = 0.f; }

    // accumulators: this thread owns j in {jj, jj+16}, c in [cbase, cbase+32)
    const int jj = tid & 15;
    const int cbase = (tid >> 4) * 32;
    float acc0[32], acc1[32];
#pragma unroll
    for (int q = 0; q < 32; q++) { acc0[q] = 0.f; acc1[q] = 0.f; }
    __syncthreads();

    const int jb = warp * 4;             // S-phase: warp owns j = jb..jb+3, lane = i

    for (int i0 = 0; i0 < NN; i0 += 32) {
        // load key tile
        const float* fbase = d_f + ((size_t)b * NN + i0) * CQ;
        for (int e = tid; e < 32 * 64; e += 256) fs[e >> 6][e & 63] = fbase[e];
        __syncthreads();

        // S[jb+q][lane] = f[lane] . g[jb+q]
        float sv[4] = {0.f, 0.f, 0.f, 0.f};
#pragma unroll
        for (int d = 0; d < 64; d += 4) {
            float4 fv = *(const float4*)&fs[lane][d];
#pragma unroll
            for (int q = 0; q < 4; q++) {
                float4 gv = *(const float4*)&gs[jb + q][d];
                sv[q] += fv.x * gv.x + fv.y * gv.y + fv.z * gv.z + fv.w * gv.w;
            }
        }

        // online softmax stats (warp-level, lane = key index)
#pragma unroll
        for (int q = 0; q < 4; q++) {
            float v = sv[q];
#pragma unroll
            for (int o = 16; o > 0; o >>= 1) v = fmaxf(v, __shfl_xor_sync(0xFFFFFFFFu, v, o));
            const float mold = m_s[jb + q];
            const float mnew = fmaxf(mold, v);
            const float p = __expf(sv[q] - mnew);
            float ssum = p;
#pragma unroll
            for (int o = 16; o > 0; o >>= 1) ssum += __shfl_xor_sync(0xFFFFFFFFu, ssum, o);
            const float sc = __expf(mold - mnew);
            __syncwarp();
            if (lane == 0) {
                m_s[jb + q] = mnew;
                l_s[jb + q] = l_s[jb + q] * sc + ssum;
                scale_s[jb + q] = sc;
            }
            Ps[jb + q][lane] = p;
        }
        __syncthreads();

        // acc update: acc = acc*scale + P @ h_tile (h streamed from global, L1-broadcast)
        const float sc0 = scale_s[jj];
        const float sc1 = scale_s[jj + 16];
#pragma unroll
        for (int q = 0; q < 32; q++) { acc0[q] *= sc0; acc1[q] *= sc1; }
        const float* hbase = d_h + ((size_t)b * NN + i0) * CC + cbase;
#pragma unroll 4
        for (int i = 0; i < 32; i++) {
            const float p0 = Ps[jj][i];
            const float p1 = Ps[jj + 16][i];
            const float4* hp = (const float4*)(hbase + (size_t)i * CC);
#pragma unroll
            for (int q = 0; q < 8; q++) {
                float4 hv = hp[q];
                acc0[q * 4 + 0] += p0 * hv.x; acc0[q * 4 + 1] += p0 * hv.y;
                acc0[q * 4 + 2] += p0 * hv.z; acc0[q * 4 + 3] += p0 * hv.w;
                acc1[q * 4 + 0] += p1 * hv.x; acc1[q * 4 + 1] += p1 * hv.y;
                acc1[q * 4 + 2] += p1 * hv.z; acc1[q * 4 + 3] += p1 * hv.w;
            }
        }
        __syncthreads();
    }

    // epilogue: y[b,c,j] = gamma * acc/l + x[b,c,j]
    const float gam = gamma[0];
    const float r0 = 1.f / l_s[jj];
    const float r1 = 1.f / l_s[jj + 16];
    const size_t xb = (size_t)b * CC * NN;
#pragma unroll
    for (int q = 0; q < 32; q++) {
        const int c = cbase + q;
        const size_t idx0 = xb + (size_t)c * NN + j0 + jj;
        const size_t idx1 = idx0 + 16;
        out[idx0] = gam * acc0[q] * r0 + x[idx0];
        out[idx1] = gam * acc1[q] * r1 + x[idx1];
    }
}

// ---------------- launch ---------------------------------------------------------
extern "C" void kernel_launch(void* const* d_in, const int* in_sizes, int n_in,
                              void* d_out, int out_size) {
    (void)in_sizes; (void)n_in; (void)out_size;
    const float* x     = (const float*)d_in[0];
    const float* Wf    = (const float*)d_in[1];
    const float* bf    = (const float*)d_in[2];
    const float* Wg    = (const float*)d_in[3];
    const float* bg    = (const float*)d_in[4];
    const float* Wh    = (const float*)d_in[5];
    const float* bh    = (const float*)d_in[6];
    const float* gamma = (const float*)d_in[7];
    const float* uf    = (const float*)d_in[8];
    const float* ug    = (const float*)d_in[9];
    const float* uh    = (const float*)d_in[10];
    float* out = (float*)d_out;

    sigma_kernel<<<3, 512>>>(Wf, Wg, Wh, uf, ug, uh);
    proj_kernel<<<dim3(NN / 64, 10, BB), dim3(16, 16)>>>(x, Wf, bf, Wg, bg, Wh, bh);
    attn_kernel<<<dim3(NN / 32, BB), 256>>>(x, gamma, out);
}

// round 2
// speedup vs baseline: 1.0858x; 1.0858x over previous
#include <cuda_runtime.h>
#include <math.h>

#define BB 8
#define CC 512
#define CQ 64
#define NN 4096   // H*W = 64*64

typedef unsigned long long u64;

// ---------------- packed fp32x2 helpers (sm_100a dual-fp32 pipe) ----------------
__device__ __forceinline__ u64 pack2(float lo, float hi) {
    u64 r; asm("mov.b64 %0, {%1, %2};" : "=l"(r) : "f"(lo), "f"(hi)); return r;
}
__device__ __forceinline__ void unpack2(u64 v, float& lo, float& hi) {
    asm("mov.b64 {%0, %1}, %2;" : "=f"(lo), "=f"(hi) : "l"(v));
}
__device__ __forceinline__ u64 ffma2(u64 a, u64 b, u64 c) {
    u64 d; asm("fma.rn.f32x2 %0, %1, %2, %3;" : "=l"(d) : "l"(a), "l"(b), "l"(c)); return d;
}
__device__ __forceinline__ u64 fmul2(u64 a, u64 b) {
    u64 d; asm("mul.rn.f32x2 %0, %1, %2;" : "=l"(d) : "l"(a), "l"(b)); return d;
}

// ---------------- scratch (static device arrays: allowed) ----------------
__device__ float d_f[(size_t)BB * NN * CQ];          // keys   f : (b, i, d)  8 MB
__device__ float d_g[(size_t)BB * NN * CQ];          // queries g: (b, j, d)  8 MB
__device__ float d_h[(size_t)BB * NN * CC];          // values h : (b, i, c) 64 MB
__device__ float d_rsig[3];                          // 1/sigma for Wf, Wg, Wh

// ---------------- 1) spectral sigma: sigma = ||W v||, v = normalize(W^T u) -----
__global__ void sigma_kernel(const float* __restrict__ Wf, const float* __restrict__ Wg,
                             const float* __restrict__ Wh, const float* __restrict__ uf,
                             const float* __restrict__ ug, const float* __restrict__ uh) {
    const int w = blockIdx.x;
    const float* W; const float* u; int M;
    if (w == 0)      { W = Wf; u = uf; M = CQ; }
    else if (w == 1) { W = Wg; u = ug; M = CQ; }
    else             { W = Wh; u = uh; M = CC; }
    const int K = CC;

    __shared__ float t[CC];
    __shared__ float red[CC];
    __shared__ float wsum[16];
    __shared__ float vnorm;
    const int tid = threadIdx.x;  // 512 threads
    const int lane = tid & 31, warp = tid >> 5;

    // t = W^T u  (thread per column -> coalesced across threads)
    float acc = 0.f;
    for (int m = 0; m < M; m++) acc += W[m * K + tid] * u[m];
    t[tid] = acc;
    red[tid] = acc * acc;
    __syncthreads();
    for (int s = 256; s > 0; s >>= 1) { if (tid < s) red[tid] += red[tid + s]; __syncthreads(); }
    if (tid == 0) vnorm = sqrtf(red[0]) + 1e-12f;
    __syncthreads();
    t[tid] *= (1.f / vnorm);   // t := v
    __syncthreads();

    // w = W v : warp per row, lane-strided k (coalesced). sigma = ||w||^2/(||w||+eps)
    float local = 0.f;
    for (int m = warp; m < M; m += 16) {
        const float* Wr = W + (size_t)m * K;
        float a = 0.f;
#pragma unroll 4
        for (int k = lane; k < K; k += 32) a += Wr[k] * t[k];
#pragma unroll
        for (int o = 16; o > 0; o >>= 1) a += __shfl_xor_sync(0xFFFFFFFFu, a, o);
        local += a * a;
    }
    if (lane == 0) wsum[warp] = local;
    __syncthreads();
    if (tid == 0) {
        float nw2 = 0.f;
#pragma unroll
        for (int i = 0; i < 16; i++) nw2 += wsum[i];
        float nw = sqrtf(nw2);
        float sigma = nw2 / (nw + 1e-12f);
        d_rsig[w] = 1.f / sigma;
    }
}

// ---------------- 2) fused projection GEMM: (f,g,h) = W_seg/sigma @ x + b -------
__global__ void __launch_bounds__(256) proj_kernel(
    const float* __restrict__ x,
    const float* __restrict__ Wf, const float* __restrict__ bf,
    const float* __restrict__ Wg, const float* __restrict__ bg,
    const float* __restrict__ Wh, const float* __restrict__ bh) {
    const int K = CC;
    const int n0 = blockIdx.x * 64;
    const int o0 = blockIdx.y * 64;     // combined o in [0,640)
    const int b  = blockIdx.z;

    const float* W; const float* bias; int seg, orow0;
    if (o0 < 64)       { seg = 0; W = Wf; bias = bf; orow0 = o0; }
    else if (o0 < 128) { seg = 1; W = Wg; bias = bg; orow0 = o0 - 64; }
    else               { seg = 2; W = Wh; bias = bh; orow0 = o0 - 128; }

    __shared__ float Ws[32][69];   // [kk][oo]
    __shared__ float xs[32][68];   // [kk][nn], 272B rows -> 16B aligned

    const int tid = threadIdx.y * 16 + threadIdx.x;
    const int tx = threadIdx.x, ty = threadIdx.y;

    u64 accp[4][2];
#pragma unroll
    for (int i = 0; i < 4; i++) { accp[i][0] = 0ull; accp[i][1] = 0ull; }

    const size_t xbase = (size_t)b * CC * NN;

    for (int kc = 0; kc < K; kc += 32) {
#pragma unroll
        for (int r = 0; r < 8; r++) {
            int e = tid + 256 * r;
            int kk = e >> 6, nn = e & 63;
            xs[kk][nn] = x[xbase + (size_t)(kc + kk) * NN + n0 + nn];
        }
#pragma unroll
        for (int r = 0; r < 8; r++) {
            int e = tid + 256 * r;
            int kk = e & 31, oo = e >> 5;
            Ws[kk][oo] = W[(size_t)(orow0 + oo) * K + kc + kk];
        }
        __syncthreads();
#pragma unroll
        for (int kk = 0; kk < 32; kk++) {
            ulonglong2 bv = *(const ulonglong2*)&xs[kk][tx * 4];
#pragma unroll
            for (int i = 0; i < 4; i++) {
                float a = Ws[kk][ty * 4 + i];
                u64 A = pack2(a, a);
                accp[i][0] = ffma2(A, bv.x, accp[i][0]);
                accp[i][1] = ffma2(A, bv.y, accp[i][1]);
            }
        }
        __syncthreads();
    }

    const float rs = d_rsig[seg];
#pragma unroll
    for (int i = 0; i < 4; i++) {
        const int orow = orow0 + ty * 4 + i;
        const float bia = bias[orow];
        float v[4];
        unpack2(accp[i][0], v[0], v[1]);
        unpack2(accp[i][1], v[2], v[3]);
#pragma unroll
        for (int j = 0; j < 4; j++) {
            const int n = n0 + tx * 4 + j;
            const float val = v[j] * rs + bia;
            if (seg == 0)      d_f[((size_t)b * NN + n) * CQ + orow] = val;
            else if (seg == 1) d_g[((size_t)b * NN + n) * CQ + orow] = val;
            else               d_h[((size_t)b * NN + n) * CC + orow] = val;
        }
    }
}

// ---------------- 3) flash attention (packed fp32x2 math) ----------------------
__global__ void __launch_bounds__(256, 2) attn_kernel(
    const float* __restrict__ x, const float* __restrict__ gamma,
    float* __restrict__ out) {
    const int b  = blockIdx.y;
    const int j0 = blockIdx.x * 32;
    const int tid = threadIdx.x;
    const int lane = tid & 31, warp = tid >> 5;

    __shared__ float gs[32][68];         // g[j][d], 272B rows
    __shared__ float fs[32][68];         // f[i][d]
    __shared__ float Ps[32][36];         // exp(S - mnew), 144B rows -> float4 aligned
    __shared__ float m_s[32], l_s[32], scale_s[32];

    const float* gbase = d_g + ((size_t)b * NN + j0) * CQ;
    for (int e = tid; e < 32 * 64; e += 256) gs[e >> 6][e & 63] = gbase[e];
    if (tid < 32) { m_s[tid] = -INFINITY; l_s[tid] = 0.f; }

    // accumulators: thread owns j in {jj, jj+16}, channels [cbase, cbase+32) as 16 f32x2
    const int jj = tid & 15;
    const int cbase = (tid >> 4) * 32;
    u64 acc0[16], acc1[16];
#pragma unroll
    for (int q = 0; q < 16; q++) { acc0[q] = 0ull; acc1[q] = 0ull; }
    __syncthreads();

    const int jb = warp * 4;             // S-phase: warp owns j = jb..jb+3, lane = key i

    for (int i0 = 0; i0 < NN; i0 += 32) {
        const float* fbase = d_f + ((size_t)b * NN + i0) * CQ;
        for (int e = tid; e < 32 * 64; e += 256) fs[e >> 6][e & 63] = fbase[e];
        __syncthreads();

        // S[jb+q][lane] = f[lane] . g[jb+q]  (packed pairwise dot)
        u64 sa[4] = {0ull, 0ull, 0ull, 0ull};
#pragma unroll
        for (int d = 0; d < 64; d += 4) {
            ulonglong2 fv = *(const ulonglong2*)&fs[lane][d];
#pragma unroll
            for (int q = 0; q < 4; q++) {
                ulonglong2 gv = *(const ulonglong2*)&gs[jb + q][d];
                sa[q] = ffma2(fv.x, gv.x, sa[q]);
                sa[q] = ffma2(fv.y, gv.y, sa[q]);
            }
        }
        float sv[4];
#pragma unroll
        for (int q = 0; q < 4; q++) { float lo, hi; unpack2(sa[q], lo, hi); sv[q] = lo + hi; }

        // online softmax stats (warp-level, lane = key index)
#pragma unroll
        for (int q = 0; q < 4; q++) {
            float v = sv[q];
#pragma unroll
            for (int o = 16; o > 0; o >>= 1) v = fmaxf(v, __shfl_xor_sync(0xFFFFFFFFu, v, o));
            const float mold = m_s[jb + q];
            const float mnew = fmaxf(mold, v);
            const float p = __expf(sv[q] - mnew);
            float ssum = p;
#pragma unroll
            for (int o = 16; o > 0; o >>= 1) ssum += __shfl_xor_sync(0xFFFFFFFFu, ssum, o);
            const float sc = __expf(mold - mnew);
            __syncwarp();
            if (lane == 0) {
                m_s[jb + q] = mnew;
                l_s[jb + q] = l_s[jb + q] * sc + ssum;
                scale_s[jb + q] = sc;
            }
            Ps[jb + q][lane] = p;
        }
        __syncthreads();

        // acc = acc*scale + P @ h_tile (packed FFMA2; h streamed, L1-broadcast)
        const u64 SC0 = pack2(scale_s[jj], scale_s[jj]);
        const u64 SC1 = pack2(scale_s[jj + 16], scale_s[jj + 16]);
#pragma unroll
        for (int q = 0; q < 16; q++) { acc0[q] = fmul2(acc0[q], SC0); acc1[q] = fmul2(acc1[q], SC1); }

        const float* hbase = d_h + ((size_t)b * NN + i0) * CC + cbase;
#pragma unroll
        for (int i4 = 0; i4 < 32; i4 += 4) {
            float4 p0v = *(const float4*)&Ps[jj][i4];
            float4 p1v = *(const float4*)&Ps[jj + 16][i4];
            const float* hrow = hbase + (size_t)i4 * CC;
#pragma unroll
            for (int t = 0; t < 4; t++) {
                const float p0 = (t == 0) ? p0v.x : (t == 1) ? p0v.y : (t == 2) ? p0v.z : p0v.w;
                const float p1 = (t == 0) ? p1v.x : (t == 1) ? p1v.y : (t == 2) ? p1v.z : p1v.w;
                const u64 P0 = pack2(p0, p0);
                const u64 P1 = pack2(p1, p1);
                const ulonglong2* hp = (const ulonglong2*)(hrow + (size_t)t * CC);
#pragma unroll
                for (int q = 0; q < 8; q++) {
                    ulonglong2 hv = hp[q];
                    acc0[q * 2 + 0] = ffma2(P0, hv.x, acc0[q * 2 + 0]);
                    acc0[q * 2 + 1] = ffma2(P0, hv.y, acc0[q * 2 + 1]);
                    acc1[q * 2 + 0] = ffma2(P1, hv.x, acc1[q * 2 + 0]);
                    acc1[q * 2 + 1] = ffma2(P1, hv.y, acc1[q * 2 + 1]);
                }
            }
        }
        __syncthreads();
    }

    // epilogue: y[b,c,j] = gamma * acc/l + x[b,c,j]
    const float gam = gamma[0];
    const float r0 = 1.f / l_s[jj];
    const float r1 = 1.f / l_s[jj + 16];
    const size_t xb = (size_t)b * CC * NN;
#pragma unroll
    for (int q = 0; q < 16; q++) {
        float a0lo, a0hi, a1lo, a1hi;
        unpack2(acc0[q], a0lo, a0hi);
        unpack2(acc1[q], a1lo, a1hi);
        const int c = cbase + q * 2;
        const size_t i00 = xb + (size_t)c * NN + j0 + jj;
        const size_t i01 = i00 + NN;        // c+1, same j
        out[i00]      = gam * a0lo * r0 + x[i00];
        out[i01]      = gam * a0hi * r0 + x[i01];
        out[i00 + 16] = gam * a1lo * r1 + x[i00 + 16];
        out[i01 + 16] = gam * a1hi * r1 + x[i01 + 16];
    }
}

// ---------------- launch ---------------------------------------------------------
extern "C" void kernel_launch(void* const* d_in, const int* in_sizes, int n_in,
                              void* d_out, int out_size) {
    (void)in_sizes; (void)n_in; (void)out_size;
    const float* x     = (const float*)d_in[0];
    const float* Wf    = (const float*)d_in[1];
    const float* bf    = (const float*)d_in[2];
    const float* Wg    = (const float*)d_in[3];
    const float* bg    = (const float*)d_in[4];
    const float* Wh    = (const float*)d_in[5];
    const float* bh    = (const float*)d_in[6];
    const float* gamma = (const float*)d_in[7];
    const float* uf    = (const float*)d_in[8];
    const float* ug    = (const float*)d_in[9];
    const float* uh    = (const float*)d_in[10];
    float* out = (float*)d_out;

    sigma_kernel<<<3, 512>>>(Wf, Wg, Wh, uf, ug, uh);
    proj_kernel<<<dim3(NN / 64, 10, BB), dim3(16, 16)>>>(x, Wf, bf, Wg, bg, Wh, bh);
    attn_kernel<<<dim3(NN / 32, BB), 256>>>(x, gamma, out);
}

// round 5
// speedup vs baseline: 1.6523x; 1.5217x over previous
#include <cuda_runtime.h>
#include <math.h>
#include <stdint.h>

#define BB 8
#define CC 512
#define CQ 64
#define NN 4096   // H*W

typedef unsigned long long u64;

// ---------------- packed fp32x2 helpers ----------------
__device__ __forceinline__ u64 pack2(float lo, float hi) {
    u64 r; asm("mov.b64 %0, {%1, %2};" : "=l"(r) : "f"(lo), "f"(hi)); return r;
}
__device__ __forceinline__ void unpack2(u64 v, float& lo, float& hi) {
    asm("mov.b64 {%0, %1}, %2;" : "=f"(lo), "=f"(hi) : "l"(v));
}
__device__ __forceinline__ u64 ffma2(u64 a, u64 b, u64 c) {
    u64 d; asm("fma.rn.f32x2 %0, %1, %2, %3;" : "=l"(d) : "l"(a), "l"(b), "l"(c)); return d;
}
__device__ __forceinline__ u64 fmul2(u64 a, u64 b) {
    u64 d; asm("mul.rn.f32x2 %0, %1, %2;" : "=l"(d) : "l"(a), "l"(b)); return d;
}

// ---------------- cp.async helpers ----------------
__device__ __forceinline__ uint32_t smem_u32(const void* p) {
    uint32_t a;
    asm("{ .reg .u64 t; cvta.to.shared.u64 t, %1; cvt.u32.u64 %0, t; }" : "=r"(a) : "l"(p));
    return a;
}
__device__ __forceinline__ void cp16(uint32_t s, const void* g) {
    asm volatile("cp.async.cg.shared.global [%0], [%1], 16;" :: "r"(s), "l"(g));
}
#define CP_COMMIT()  asm volatile("cp.async.commit_group;" ::: "memory")
#define CP_WAIT(n)   asm volatile("cp.async.wait_group %0;" :: "n"(n) : "memory")

// ---------------- scratch (80 MB total — matches the R2 profile that passed) ----
__device__ float d_f[(size_t)BB * CQ * NN];          // fT: (b, d, i)  8 MB
__device__ float d_g[(size_t)BB * CQ * NN];          // gT: (b, d, j)  8 MB
__device__ float d_h[(size_t)BB * NN * CC];          // h : (b, i, c) 64 MB
__device__ float d_rsig[3];

// ---------------- 1) spectral sigma ----------------
__global__ void sigma_kernel(const float* __restrict__ Wf, const float* __restrict__ Wg,
                             const float* __restrict__ Wh, const float* __restrict__ uf,
                             const float* __restrict__ ug, const float* __restrict__ uh) {
    const int w = blockIdx.x;
    const float* W; const float* u; int M;
    if (w == 0)      { W = Wf; u = uf; M = CQ; }
    else if (w == 1) { W = Wg; u = ug; M = CQ; }
    else             { W = Wh; u = uh; M = CC; }
    const int K = CC;

    __shared__ float t[CC];
    __shared__ float red[CC];
    __shared__ float wsum[16];
    __shared__ float vnorm;
    const int tid = threadIdx.x;
    const int lane = tid & 31, warp = tid >> 5;

    float acc = 0.f;
#pragma unroll 8
    for (int m = 0; m < M; m++) acc += W[m * K + tid] * u[m];
    t[tid] = acc;
    red[tid] = acc * acc;
    __syncthreads();
    for (int s = 256; s > 0; s >>= 1) { if (tid < s) red[tid] += red[tid + s]; __syncthreads(); }
    if (tid == 0) vnorm = sqrtf(red[0]) + 1e-12f;
    __syncthreads();
    t[tid] *= (1.f / vnorm);
    __syncthreads();

    float local = 0.f;
    for (int m = warp; m < M; m += 16) {
        const float* Wr = W + (size_t)m * K;
        float a = 0.f;
#pragma unroll 4
        for (int k = lane; k < K; k += 32) a += Wr[k] * t[k];
#pragma unroll
        for (int o = 16; o > 0; o >>= 1) a += __shfl_xor_sync(0xFFFFFFFFu, a, o);
        local += a * a;
    }
    if (lane == 0) wsum[warp] = local;
    __syncthreads();
    if (tid == 0) {
        float nw2 = 0.f;
#pragma unroll
        for (int i = 0; i < 16; i++) nw2 += wsum[i];
        float nw = sqrtf(nw2);
        d_rsig[w] = (nw + 1e-12f) / nw2;   // 1/sigma
    }
}

// ---------------- 2) fused projections; f,g stored transposed (b,d,n) ----------------
__global__ void __launch_bounds__(256) proj_kernel(
    const float* __restrict__ x,
    const float* __restrict__ Wf, const float* __restrict__ bf,
    const float* __restrict__ Wg, const float* __restrict__ bg,
    const float* __restrict__ Wh, const float* __restrict__ bh) {
    const int K = CC;
    const int n0 = blockIdx.x * 64;
    const int o0 = blockIdx.y * 64;
    const int b  = blockIdx.z;

    const float* W; const float* bias; int seg, orow0;
    if (o0 < 64)       { seg = 0; W = Wf; bias = bf; orow0 = o0; }
    else if (o0 < 128) { seg = 1; W = Wg; bias = bg; orow0 = o0 - 64; }
    else               { seg = 2; W = Wh; bias = bh; orow0 = o0 - 128; }

    __shared__ float Ws[32][69];
    __shared__ float xs[32][68];

    const int tid = threadIdx.y * 16 + threadIdx.x;
    const int tx = threadIdx.x, ty = threadIdx.y;

    u64 accp[4][2];
#pragma unroll
    for (int i = 0; i < 4; i++) { accp[i][0] = 0ull; accp[i][1] = 0ull; }

    const size_t xbase = (size_t)b * CC * NN;

    for (int kc = 0; kc < K; kc += 32) {
#pragma unroll
        for (int r = 0; r < 8; r++) {
            int e = tid + 256 * r;
            int kk = e >> 6, nn = e & 63;
            xs[kk][nn] = x[xbase + (size_t)(kc + kk) * NN + n0 + nn];
        }
#pragma unroll
        for (int r = 0; r < 8; r++) {
            int e = tid + 256 * r;
            int kk = e & 31, oo = e >> 5;
            Ws[kk][oo] = W[(size_t)(orow0 + oo) * K + kc + kk];
        }
        __syncthreads();
#pragma unroll
        for (int kk = 0; kk < 32; kk++) {
            ulonglong2 bv = *(const ulonglong2*)&xs[kk][tx * 4];
#pragma unroll
            for (int i = 0; i < 4; i++) {
                float a = Ws[kk][ty * 4 + i];
                u64 A = pack2(a, a);
                accp[i][0] = ffma2(A, bv.x, accp[i][0]);
                accp[i][1] = ffma2(A, bv.y, accp[i][1]);
            }
        }
        __syncthreads();
    }

    const float rs = d_rsig[seg];
    const u64 rs2 = pack2(rs, rs);
#pragma unroll
    for (int i = 0; i < 4; i++) {
        const int orow = orow0 + ty * 4 + i;
        const float bia = bias[orow];
        const u64 b2 = pack2(bia, bia);
        u64 r0 = ffma2(accp[i][0], rs2, b2);
        u64 r1 = ffma2(accp[i][1], rs2, b2);
        if (seg < 2) {
            float* dst = (seg == 0 ? d_f : d_g) + ((size_t)b * CQ + orow) * NN + n0 + tx * 4;
            *(u64*)dst = r0;
            *(u64*)(dst + 2) = r1;
        } else {
            float v[4];
            unpack2(r0, v[0], v[1]);
            unpack2(r1, v[2], v[3]);
#pragma unroll
            for (int j = 0; j < 4; j++)
                d_h[((size_t)b * NN + n0 + tx * 4 + j) * CC + orow] = v[j];
        }
    }
}

// ---------------- 3) tiled flash attention --------------------------------------
// Block: 128 queries (j), 256 channels (c-half), batch b. 256 threads.
// Thread: 8 j (4 packed j-pairs) x 16 c. Key tiles of 32 streamed via cp.async.
//
// smem (float offsets):
#define GS_OFF   0        // gs[64][128]            32.0 KB
#define HS0_OFF  8192     // hs buf0 [32][260]      33.3 KB
#define HS1_OFF  16512    // hs buf1
#define FS0_OFF  24832    // fs buf0 [64][32]        8.0 KB
#define FS1_OFF  26880    // fs buf1
#define PS_OFF   28928    // Ps[32][130]            16.6 KB
#define SMEM_FLOATS 33088 // 132352 bytes

extern __shared__ float sm_attn[];

__global__ void __launch_bounds__(256, 1) attn_kernel(
    const float* __restrict__ x, const float* __restrict__ gamma,
    float* __restrict__ out) {
    const int b  = blockIdx.z;
    const int c0 = blockIdx.y * 256;
    const int j0 = blockIdx.x * 128;
    const int tid = threadIdx.x;
    const int tx = tid & 15, ty = tid >> 4;
    const int jloc = 2 * ty;                    // + 32*mj

    const float* gT = d_g + (size_t)b * CQ * NN;
    const float* fT = d_f + (size_t)b * CQ * NN;
    const float* hb = d_h + (size_t)b * NN * CC;

    float* gs = sm_attn + GS_OFF;
    float* Ps = sm_attn + PS_OFF;

    // resident g tile: gs[d][j]
#pragma unroll
    for (int r = 0; r < 8; r++) {
        int e = tid + 256 * r;                  // 2048 float4
        int d = e >> 5, jc = (e & 31) * 4;
        *(float4*)&gs[d * 128 + jc] = *(const float4*)&gT[(size_t)d * NN + j0 + jc];
    }

    u64 acc[4][16];
#pragma unroll
    for (int mj = 0; mj < 4; mj++)
#pragma unroll
        for (int q = 0; q < 16; q++) acc[mj][q] = 0ull;
    float mrow[8], lrow[8];
#pragma unroll
    for (int r = 0; r < 8; r++) { mrow[r] = -INFINITY; lrow[r] = 0.f; }

    // prefetch tile 0
    {
        float* fsb = sm_attn + FS0_OFF;
        float* hsb = sm_attn + HS0_OFF;
#pragma unroll
        for (int r = 0; r < 2; r++) {
            int e = tid + 256 * r;              // 512 chunks
            int d = e >> 3, ic = (e & 7) * 4;
            cp16(smem_u32(&fsb[d * 32 + ic]), &fT[(size_t)d * NN + ic]);
        }
#pragma unroll
        for (int r = 0; r < 8; r++) {
            int e = tid + 256 * r;              // 2048 chunks
            int i = e >> 6, cc = (e & 63) * 4;
            cp16(smem_u32(&hsb[i * 260 + cc]), &hb[(size_t)i * CC + c0 + cc]);
        }
        CP_COMMIT();
    }
    __syncthreads();                            // gs visible

    for (int t = 0; t < 128; t++) {
        const int buf = t & 1;
        if (t + 1 < 128) {                      // prefetch next tile
            float* fsb = sm_attn + (buf ? FS0_OFF : FS1_OFF);
            float* hsb = sm_attn + (buf ? HS0_OFF : HS1_OFF);
            const int i0 = (t + 1) * 32;
#pragma unroll
            for (int r = 0; r < 2; r++) {
                int e = tid + 256 * r;
                int d = e >> 3, ic = (e & 7) * 4;
                cp16(smem_u32(&fsb[d * 32 + ic]), &fT[(size_t)d * NN + i0 + ic]);
            }
#pragma unroll
            for (int r = 0; r < 8; r++) {
                int e = tid + 256 * r;
                int i = e >> 6, cc = (e & 63) * 4;
                cp16(smem_u32(&hsb[i * 260 + cc]), &hb[(size_t)(i0 + i) * CC + c0 + cc]);
            }
            CP_COMMIT();
            CP_WAIT(1);                         // tile t group complete
        } else {
            CP_WAIT(0);
        }
        __syncthreads();

        const float* fsb = sm_attn + (buf ? FS1_OFF : FS0_OFF);
        const float* hsb = sm_attn + (buf ? HS1_OFF : HS0_OFF);

        // --- S phase: sa[mj][ii] = (S[j][i_ii], S[j+1][i_ii]), i_ii = 2*tx+ii ---
        u64 sa[4][2];
#pragma unroll
        for (int mj = 0; mj < 4; mj++) { sa[mj][0] = 0ull; sa[mj][1] = 0ull; }
#pragma unroll 8
        for (int d = 0; d < 64; d++) {
            u64 fp = *(const u64*)&fsb[d * 32 + 2 * tx];
            float f0, f1; unpack2(fp, f0, f1);
            u64 F0 = pack2(f0, f0), F1 = pack2(f1, f1);
#pragma unroll
            for (int mj = 0; mj < 4; mj++) {
                u64 ga = *(const u64*)&gs[d * 128 + jloc + 32 * mj];
                sa[mj][0] = ffma2(ga, F0, sa[mj][0]);
                sa[mj][1] = ffma2(ga, F1, sa[mj][1]);
            }
        }

        // --- online softmax (reduce over tx = key lanes), Ps store, acc rescale ---
#pragma unroll
        for (int mj = 0; mj < 4; mj++) {
            float sA0, sB0, sA1, sB1;
            unpack2(sa[mj][0], sA0, sB0);       // i=2tx:   rows j, j+1
            unpack2(sa[mj][1], sA1, sB1);       // i=2tx+1
            // row A (j = j0 + jloc + 32*mj)
            float tmA = fmaxf(sA0, sA1);
#pragma unroll
            for (int o = 1; o < 16; o <<= 1) tmA = fmaxf(tmA, __shfl_xor_sync(0xFFFFFFFFu, tmA, o));
            float mA = fmaxf(mrow[2 * mj], tmA);
            float scA = __expf(mrow[2 * mj] - mA);
            float pA0 = __expf(sA0 - mA), pA1 = __expf(sA1 - mA);
            float suA = pA0 + pA1;
#pragma unroll
            for (int o = 1; o < 16; o <<= 1) suA += __shfl_xor_sync(0xFFFFFFFFu, suA, o);
            lrow[2 * mj] = lrow[2 * mj] * scA + suA;
            mrow[2 * mj] = mA;
            // row B (j+1)
            float tmB = fmaxf(sB0, sB1);
#pragma unroll
            for (int o = 1; o < 16; o <<= 1) tmB = fmaxf(tmB, __shfl_xor_sync(0xFFFFFFFFu, tmB, o));
            float mB = fmaxf(mrow[2 * mj + 1], tmB);
            float scB = __expf(mrow[2 * mj + 1] - mB);
            float pB0 = __expf(sB0 - mB), pB1 = __expf(sB1 - mB);
            float suB = pB0 + pB1;
#pragma unroll
            for (int o = 1; o < 16; o <<= 1) suB += __shfl_xor_sync(0xFFFFFFFFu, suB, o);
            lrow[2 * mj + 1] = lrow[2 * mj + 1] * scB + suB;
            mrow[2 * mj + 1] = mB;

            // Ps[i][j-pair]  (warp-local: same ty set as the PV consumer)
            *(u64*)&Ps[(2 * tx) * 130 + jloc + 32 * mj]     = pack2(pA0, pB0);
            *(u64*)&Ps[(2 * tx + 1) * 130 + jloc + 32 * mj] = pack2(pA1, pB1);

            const u64 scp = pack2(scA, scB);
#pragma unroll
            for (int q = 0; q < 16; q++) acc[mj][q] = fmul2(acc[mj][q], scp);
        }
        __syncwarp();

        // --- PV phase: acc[mj][q] += P[j-pair][k] * h[k][c] ---
#pragma unroll 4
        for (int k = 0; k < 32; k++) {
            u64 pa[4];
#pragma unroll
            for (int mj = 0; mj < 4; mj++)
                pa[mj] = *(const u64*)&Ps[k * 130 + jloc + 32 * mj];
            const float* hr = &hsb[k * 260 + tx];
#pragma unroll
            for (int q = 0; q < 16; q++) {
                float hv = hr[16 * q];
                u64 H = pack2(hv, hv);
#pragma unroll
                for (int mj = 0; mj < 4; mj++)
                    acc[mj][q] = ffma2(pa[mj], H, acc[mj][q]);
            }
        }
        __syncthreads();                        // before buffers are refilled
    }

    // --- epilogue: y[b,c,j..j+1] = gamma * acc / l + x ---
    const float gam = gamma[0];
    const u64 G = pack2(gam, gam);
    u64 rl[4];
#pragma unroll
    for (int mj = 0; mj < 4; mj++)
        rl[mj] = pack2(1.f / lrow[2 * mj], 1.f / lrow[2 * mj + 1]);
    const size_t xb = (size_t)b * CC * NN;
#pragma unroll
    for (int q = 0; q < 16; q++) {
        const int c = c0 + tx + 16 * q;
        const size_t base = xb + (size_t)c * NN + j0 + jloc;
#pragma unroll
        for (int mj = 0; mj < 4; mj++) {
            const size_t idx = base + 32 * mj;
            u64 xv = *(const u64*)&x[idx];
            u64 t2 = fmul2(acc[mj][q], rl[mj]);
            *(u64*)&out[idx] = ffma2(t2, G, xv);
        }
    }
}

// ---------------- launch ----------------
extern "C" void kernel_launch(void* const* d_in, const int* in_sizes, int n_in,
                              void* d_out, int out_size) {
    (void)in_sizes; (void)n_in; (void)out_size;
    const float* x     = (const float*)d_in[0];
    const float* Wf    = (const float*)d_in[1];
    const float* bf    = (const float*)d_in[2];
    const float* Wg    = (const float*)d_in[3];
    const float* bg    = (const float*)d_in[4];
    const float* Wh    = (const float*)d_in[5];
    const float* bh    = (const float*)d_in[6];
    const float* gamma = (const float*)d_in[7];
    const float* uf    = (const float*)d_in[8];
    const float* ug    = (const float*)d_in[9];
    const float* uh    = (const float*)d_in[10];
    float* out = (float*)d_out;

    cudaFuncSetAttribute(attn_kernel, cudaFuncAttributeMaxDynamicSharedMemorySize,
                         SMEM_FLOATS * (int)sizeof(float));

    sigma_kernel<<<3, 512>>>(Wf, Wg, Wh, uf, ug, uh);
    proj_kernel<<<dim3(NN / 64, 10, BB), dim3(16, 16)>>>(x, Wf, bf, Wg, bg, Wh, bh);
    attn_kernel<<<dim3(NN / 128, 2, BB), 256, SMEM_FLOATS * sizeof(float)>>>(x, gamma, out);
}